// round 14
// baseline (speedup 1.0000x reference)
#include <cuda_runtime.h>

// ---------------- static problem geometry ----------------
#define BZ        8
#define MAXLEN    5500
#define NFT       900
// seg0: txt [0,225)     img [225,2025)
// seg1: txt [2025,2250) img [2250,4050)
// pad  [4050,5500)
// attention blocks: [0,2025) and [2025,4050); identical for all 8 batches

// output layout (flattened float32 concat of the 6-tuple)
#define OFF_LOSS   0LL
#define OFF_TOKENS 8LL
#define OFF_TXT    2816008LL
#define OFF_IMG    2860008LL
#define OFF_POS    2904008LL
#define OFF_ATTN   3036008LL

#define ATTN_F4_TOTAL 60500000u   // 8*5500*5500/4
#define ROW_F4        1375u       // 5500/4

#define LOSS_BLOCKS   8u
#define TOK_BLOCKS    11000u      // 8*5500*64 / 256
#define ATTN_BLOCKS   236329u     // ceil(60,500,000 / 256)
#define TOK_END       (LOSS_BLOCKS + TOK_BLOCKS)           // 11008
#define IMG_ELEMS     230400u     // 3600 tokens * 64 dims per batch

// ---------------- single fused kernel, zero cross-block sync ----------------
__global__ void __launch_bounds__(256) k_fused(
        const float* __restrict__ inp,    // [32,16,60,60]
        const float* __restrict__ noise,  // [8,5500,64]
        const float* __restrict__ alphas, // [8]
        float* __restrict__ out) {

    if (blockIdx.x < LOSS_BLOCKS) {
        // ---------- loss block: batch b, self-contained recompute ----------
        const int b = blockIdx.x;
        const float a   = alphas[b];
        const float om  = 1.0f - a * a;           // 1 - a^2
        const float am1 = a - 1.0f;
        const float sig = sqrtf(om);

        // d fixed per thread (stride 256, 64 | 256)
        const int d  = threadIdx.x & 63;
        const int o0 = threadIdx.x >> 6;          // 0..3, o advances by 4
        const int p = d >> 5, q = (d >> 4) & 1, c = d & 15;

        float acc = 0.0f;
        for (int o = o0; o < 3600; o += 4) {
            const int L   = 225 + o + ((o >= 1800) ? 225 : 0);
            const int t   = b * 4 + o / NFT;
            const int rem = o % NFT;
            const int hh  = rem / 30;
            const int ww  = rem - hh * 30;
            const float x = inp[((t * 16 + c) * 60 + (hh * 2 + p)) * 60 + (ww * 2 + q)];
            const float n = noise[((size_t)b * MAXLEN + L) * 64 + d];
            const float diff = x * am1 + n * sig;
            acc += diff * diff;
        }

        __shared__ float s[256];
        s[threadIdx.x] = acc;
        __syncthreads();
#pragma unroll
        for (int st = 128; st > 0; st >>= 1) {
            if (threadIdx.x < (unsigned)st) s[threadIdx.x] += s[threadIdx.x + st];
            __syncthreads();
        }
        if (threadIdx.x == 0) out[OFF_LOSS + b] = s[0] / (om * 352000.0f);
        return;
    }

    if (blockIdx.x >= TOK_END) {
        // ---------- attention mask: 1 float4/thread, sequential sweep (proven best) ----------
        const unsigned i4 = (blockIdx.x - TOK_END) * 256u + threadIdx.x;
        if (i4 >= ATTN_F4_TOTAL) return;
        const unsigned rowall = i4 / ROW_F4;          // 0 .. 43999
        const unsigned col4   = i4 - rowall * ROW_F4;
        const unsigned row    = rowall % MAXLEN;

        int lo, hi;
        if (row < 2025u)      { lo = 0;    hi = 2025; }
        else if (row < 4050u) { lo = 2025; hi = 4050; }
        else                  { lo = 0;    hi = 0; }

        const int c0 = (int)(col4 * 4u);
        float4 v;
        v.x = (c0     >= lo && c0     < hi) ? 1.0f : 0.0f;
        v.y = (c0 + 1 >= lo && c0 + 1 < hi) ? 1.0f : 0.0f;
        v.z = (c0 + 2 >= lo && c0 + 2 < hi) ? 1.0f : 0.0f;
        v.w = (c0 + 3 >= lo && c0 + 3 < hi) ? 1.0f : 0.0f;

        __stcs(reinterpret_cast<float4*>(out + OFF_ATTN) + i4, v);
        return;
    }

    // ---------- tokens + masks + position_ids (pure writers, no sync) ----------
    const unsigned tb  = blockIdx.x - LOSS_BLOCKS;          // 0 .. 10999
    const unsigned idx = tb * 256u + threadIdx.x;           // < 2,816,000
    const int d  = idx & 63;
    const int bl = idx >> 6;              // b*5500 + L
    const int b  = bl / MAXLEN;
    const int L  = bl - b * MAXLEN;

    const bool img = (L >= 225 && L < 2025) || (L >= 2250 && L < 4050);
    const bool txt = (L < 225) || (L >= 2025 && L < 2250);

    float val = 0.0f;
    if (img) {
        const int o   = L - 225 - ((L >= 2250) ? 225 : 0);  // [0,3600)
        const int t   = b * 4 + o / NFT;
        const int rem = o % NFT;
        const int hh  = rem / 30;
        const int ww  = rem - hh * 30;
        const int p = d >> 5, q = (d >> 4) & 1, c = d & 15;
        val = inp[((t * 16 + c) * 60 + (hh * 2 + p)) * 60 + (ww * 2 + q)];
    }

    out[OFF_TOKENS + idx] = val;

    if (d == 0) out[OFF_TXT + bl] = txt ? 1.0f : 0.0f;
    if (d == 1) out[OFF_IMG + bl] = img ? 1.0f : 0.0f;
    if (d >= 2 && d < 5) {
        float pv = -1.0f;
        if (img) {
            const int o = L - 225 - ((L >= 2250) ? 225 : 0);
            const int m = o % 1800;               // local index within segment
            const int fi = m / NFT;
            const int r2 = m - fi * NFT;
            const int fj = r2 / 30;
            const int fk = r2 - fj * 30;
            pv = (d == 2) ? (float)fi : (d == 3) ? (float)fj : (float)fk;
        }
        out[OFF_POS + (long long)bl * 3 + (d - 2)] = pv;
    }
}

// ---------------- launch ----------------
extern "C" void kernel_launch(void* const* d_in, const int* in_sizes, int n_in,
                              void* d_out, int out_size) {
    const float* inp    = (const float*)d_in[0];  // [1,32,16,60,60]
    const float* noise  = (const float*)d_in[1];  // [8,5500,64]
    const float* alphas = (const float*)d_in[2];  // [8]
    float* out = (float*)d_out;

    k_fused<<<LOSS_BLOCKS + TOK_BLOCKS + ATTN_BLOCKS, 256>>>(inp, noise, alphas, out);
}

// round 15
// speedup vs baseline: 1.3382x; 1.3382x over previous
#include <cuda_runtime.h>

// ---------------- static problem geometry ----------------
#define BZ        8
#define MAXLEN    5500
#define NFT       900
// seg0: txt [0,225)     img [225,2025)
// seg1: txt [2025,2250) img [2250,4050)
// pad  [4050,5500)
// attention blocks: [0,2025) and [2025,4050); identical for all 8 batches

// output layout (flattened float32 concat of the 6-tuple)
#define OFF_LOSS   0LL
#define OFF_TOKENS 8LL
#define OFF_TXT    2816008LL
#define OFF_IMG    2860008LL
#define OFF_POS    2904008LL
#define OFF_ATTN   3036008LL

#define ATTN_F4_TOTAL 60500000u   // 8*5500*5500/4
#define ROW_F4        1375u       // 5500/4

#define TOK_BLOCKS    11000u      // 8*5500*64 / 256
#define ATTN_BLOCKS   236329u     // ceil(60,500,000 / 256)

// ---------------- fused kernel (exact R2 shape + direct atomic loss) ----------------
__global__ void __launch_bounds__(256) k_fused(
        const float* __restrict__ inp,    // [32,16,60,60]
        const float* __restrict__ noise,  // [8,5500,64]
        const float* __restrict__ alphas, // [8]
        float* __restrict__ out) {

    if (blockIdx.x >= TOK_BLOCKS) {
        // ---------- attention mask: 1 float4/thread, sequential sweep (proven best) ----------
        const unsigned i4 = (blockIdx.x - TOK_BLOCKS) * 256u + threadIdx.x;
        if (i4 >= ATTN_F4_TOTAL) return;
        const unsigned rowall = i4 / ROW_F4;          // 0 .. 43999
        const unsigned col4   = i4 - rowall * ROW_F4;
        const unsigned row    = rowall % MAXLEN;

        int lo, hi;
        if (row < 2025u)      { lo = 0;    hi = 2025; }
        else if (row < 4050u) { lo = 2025; hi = 4050; }
        else                  { lo = 0;    hi = 0; }

        const int c0 = (int)(col4 * 4u);
        float4 v;
        v.x = (c0     >= lo && c0     < hi) ? 1.0f : 0.0f;
        v.y = (c0 + 1 >= lo && c0 + 1 < hi) ? 1.0f : 0.0f;
        v.z = (c0 + 2 >= lo && c0 + 2 < hi) ? 1.0f : 0.0f;
        v.w = (c0 + 3 >= lo && c0 + 3 < hi) ? 1.0f : 0.0f;

        __stcs(reinterpret_cast<float4*>(out + OFF_ATTN) + i4, v);
        return;
    }

    // ---------- tokens + masks + position_ids + loss (atomic, no fence) ----------
    const unsigned idx = blockIdx.x * 256u + threadIdx.x;   // < 2,816,000
    const int d  = idx & 63;
    const int bl = idx >> 6;              // b*5500 + L
    const int b  = bl / MAXLEN;
    const int L  = bl - b * MAXLEN;

    const bool img = (L >= 225 && L < 2025) || (L >= 2250 && L < 4050);
    const bool txt = (L < 225) || (L >= 2025 && L < 2250);

    float val = 0.0f;
    float contrib = 0.0f;

    if (img) {
        const int o   = L - 225 - ((L >= 2250) ? 225 : 0);  // [0,3600)
        const int t   = b * 4 + o / NFT;          // global latent frame
        const int rem = o % NFT;
        const int hh  = rem / 30;
        const int ww  = rem - hh * 30;
        const int p = d >> 5, q = (d >> 4) & 1, c = d & 15;
        val = inp[((t * 16 + c) * 60 + (hh * 2 + p)) * 60 + (ww * 2 + q)];

        const float a  = alphas[b];
        const float om = 1.0f - a * a;            // 1 - a^2
        const float diff = val * (a - 1.0f) + noise[idx] * sqrtf(om);
        contrib = diff * diff / (om * 352000.0f); // weighted mean over 352000 elems
    }

    out[OFF_TOKENS + idx] = val;

    if (d == 0) out[OFF_TXT + bl] = txt ? 1.0f : 0.0f;
    if (d == 1) out[OFF_IMG + bl] = img ? 1.0f : 0.0f;
    if (d >= 2 && d < 5) {
        float pv = -1.0f;
        if (img) {
            const int o = L - 225 - ((L >= 2250) ? 225 : 0);
            const int m = o % 1800;               // local index within segment
            const int fi = m / NFT;
            const int r2 = m - fi * NFT;
            const int fj = r2 / 30;
            const int fk = r2 - fj * 30;
            pv = (d == 2) ? (float)fi : (d == 3) ? (float)fj : (float)fk;
        }
        out[OFF_POS + (long long)bl * 3 + (d - 2)] = pv;
    }

    // block reduction of loss contribution (b is uniform within the block)
    __shared__ float s[256];
    s[threadIdx.x] = contrib;
    __syncthreads();
#pragma unroll
    for (int st = 128; st > 0; st >>= 1) {
        if (threadIdx.x < (unsigned)st) s[threadIdx.x] += s[threadIdx.x + st];
        __syncthreads();
    }
    // one atomic per block into the (memset-zeroed) loss slot; no fence needed
    if (threadIdx.x == 0 && s[0] != 0.0f) atomicAdd(&out[OFF_LOSS + b], s[0]);
}

// ---------------- launch ----------------
extern "C" void kernel_launch(void* const* d_in, const int* in_sizes, int n_in,
                              void* d_out, int out_size) {
    const float* inp    = (const float*)d_in[0];  // [1,32,16,60,60]
    const float* noise  = (const float*)d_in[1];  // [8,5500,64]
    const float* alphas = (const float*)d_in[2];  // [8]
    float* out = (float*)d_out;

    // zero the 8 loss accumulators (graph-capturable memset node, ~1-2us)
    cudaMemsetAsync(out + OFF_LOSS, 0, BZ * sizeof(float));

    k_fused<<<TOK_BLOCKS + ATTN_BLOCKS, 256>>>(inp, noise, alphas, out);
}